// round 1
// baseline (speedup 1.0000x reference)
#include <cuda_runtime.h>

#define N 8192
#define NITER 20
#define TOLF 1e-10f
#define MV_THREADS 256
#define MV_ROWS_PER_BLOCK 8            // 8 warps -> 8 rows per block
#define MV_BLOCKS (N / MV_ROWS_PER_BLOCK)   // 1024
#define V_THREADS 256
#define V_BLOCKS (N / V_THREADS)       // 32

// Persistent state (device globals: no allocations allowed)
__device__ float g_X[N];
__device__ float g_r[N];
__device__ float g_p[N];
__device__ float g_Ap[N];
__device__ float g_pAp_part[MV_BLOCKS];
__device__ float g_rr_part[NITER + 1][V_BLOCKS];

__device__ __forceinline__ float warp_red(float v) {
#pragma unroll
    for (int o = 16; o; o >>= 1) v += __shfl_xor_sync(0xffffffffu, v, o);
    return v;
}

// Deterministic sum of the 32 per-block ||r||^2 partials (uniform across threads,
// L1-broadcast loads; fixed order -> deterministic, consistent across blocks).
__device__ __forceinline__ float sum_rr(const float* a) {
    float s = 0.f;
#pragma unroll
    for (int i = 0; i < V_BLOCKS; i++) s += a[i];
    return s;
}

// --- Setup: X=0, r=p=RHS, rr_part[0] = per-block partials of ||RHS||^2 ---
__global__ void __launch_bounds__(V_THREADS) k_setup(const float* __restrict__ RHS) {
    int i = blockIdx.x * V_THREADS + threadIdx.x;
    float v = RHS[i];
    g_X[i] = 0.f;
    g_r[i] = v;
    g_p[i] = v;
    __shared__ float sred[V_THREADS / 32];
    float rr = warp_red(v * v);
    if ((threadIdx.x & 31) == 0) sred[threadIdx.x >> 5] = rr;
    __syncthreads();
    if (threadIdx.x == 0) {
        float s = 0.f;
#pragma unroll
        for (int w = 0; w < V_THREADS / 32; w++) s += sred[w];
        g_rr_part[0][blockIdx.x] = s;
    }
}

// --- Matvec: Ap = M p, plus per-block partials of p.Ap ---
__global__ void __launch_bounds__(MV_THREADS) k_mv(const float* __restrict__ M, int iter) {
    float rtr = sum_rr(g_rr_part[iter]);
    if (!(rtr > TOLF)) return;   // frozen: skip the 256 MB read entirely

    __shared__ float sp[N];      // full p vector: 32 KB
    __shared__ float swr[MV_ROWS_PER_BLOCK];
    for (int j = threadIdx.x; j < N; j += MV_THREADS) sp[j] = g_p[j];
    __syncthreads();

    int warp = threadIdx.x >> 5;
    int lane = threadIdx.x & 31;
    int row  = blockIdx.x * MV_ROWS_PER_BLOCK + warp;

    const float4* __restrict__ Mr = reinterpret_cast<const float4*>(M + (size_t)row * N);
    const float4* p4 = reinterpret_cast<const float4*>(sp);

    float acc = 0.f;
#pragma unroll 8
    for (int j = lane; j < N / 4; j += 32) {
        float4 m = Mr[j];
        float4 v = p4[j];
        acc = fmaf(m.x, v.x, acc);
        acc = fmaf(m.y, v.y, acc);
        acc = fmaf(m.z, v.z, acc);
        acc = fmaf(m.w, v.w, acc);
    }
    acc = warp_red(acc);
    if (lane == 0) {
        g_Ap[row] = acc;
        swr[warp] = acc * sp[row];   // contribution to p.Ap
    }
    __syncthreads();
    if (threadIdx.x == 0) {
        float s = 0.f;
#pragma unroll
        for (int w = 0; w < MV_ROWS_PER_BLOCK; w++) s += swr[w];
        g_pAp_part[blockIdx.x] = s;
    }
}

// --- Update X, r; produce rr_part[iter+1] ---
__global__ void __launch_bounds__(V_THREADS) k_xr(int iter) {
    float rtr = sum_rr(g_rr_part[iter]);
    bool active = (rtr > TOLF);          // block-uniform
    int tid = threadIdx.x;
    __shared__ float sred[V_THREADS / 32];

    if (active) {
        // Deterministic cooperative reduce of 1024 pAp partials
        float ps = 0.f;
#pragma unroll
        for (int k = 0; k < MV_BLOCKS / V_THREADS; k++)
            ps += g_pAp_part[tid + k * V_THREADS];
        ps = warp_red(ps);
        if ((tid & 31) == 0) sred[tid >> 5] = ps;
        __syncthreads();
        float pAp = 0.f;
#pragma unroll
        for (int w = 0; w < V_THREADS / 32; w++) pAp += sred[w];

        float alpha = rtr / pAp;
        int i = blockIdx.x * V_THREADS + tid;
        float pi = g_p[i];
        float xn = fmaf(alpha, pi, g_X[i]);
        float rn = fmaf(-alpha, g_Ap[i], g_r[i]);
        g_X[i] = xn;
        g_r[i] = rn;

        __syncthreads();   // reuse sred
        float rr = warp_red(rn * rn);
        if ((tid & 31) == 0) sred[tid >> 5] = rr;
        __syncthreads();
        if (tid == 0) {
            float s = 0.f;
#pragma unroll
            for (int w = 0; w < V_THREADS / 32; w++) s += sred[w];
            g_rr_part[iter + 1][blockIdx.x] = s;
        }
    } else {
        // frozen: carry rTr forward unchanged
        if (tid == 0) g_rr_part[iter + 1][blockIdx.x] = g_rr_part[iter][blockIdx.x];
    }
}

// --- Update p = r + beta * p ---
__global__ void __launch_bounds__(V_THREADS) k_p(int iter) {
    float rtr = sum_rr(g_rr_part[iter]);
    if (!(rtr > TOLF)) return;           // frozen: p unchanged
    float rtrn = sum_rr(g_rr_part[iter + 1]);
    float beta = rtrn / rtr;
    int i = blockIdx.x * V_THREADS + threadIdx.x;
    g_p[i] = fmaf(beta, g_p[i], g_r[i]);
}

// --- Final copy ---
__global__ void __launch_bounds__(V_THREADS) k_out(float* __restrict__ out) {
    int i = blockIdx.x * V_THREADS + threadIdx.x;
    out[i] = g_X[i];
}

extern "C" void kernel_launch(void* const* d_in, const int* in_sizes, int n_in,
                              void* d_out, int out_size) {
    // metadata order: X (shape only), M, RHS
    const float* M   = (const float*)d_in[1];
    const float* RHS = (const float*)d_in[2];
    float* out = (float*)d_out;

    k_setup<<<V_BLOCKS, V_THREADS>>>(RHS);
    for (int it = 0; it < NITER; it++) {
        k_mv<<<MV_BLOCKS, MV_THREADS>>>(M, it);
        k_xr<<<V_BLOCKS, V_THREADS>>>(it);
        k_p<<<V_BLOCKS, V_THREADS>>>(it);
    }
    k_out<<<V_BLOCKS, V_THREADS>>>(out);
}

// round 2
// speedup vs baseline: 1.0120x; 1.0120x over previous
#include <cuda_runtime.h>

#define N 8192
#define NITER 20
#define TOLF 1e-10f
#define GRID 1024
#define TPB 256
#define ROWS_PB 8            // one row per warp
#define NSYNC (2 * NITER + 2)

// Persistent device state (no allocations allowed)
__device__ float g_r[N];
__device__ float g_pap[GRID];
__device__ float g_rr[GRID];
__device__ unsigned g_sync[NSYNC];

__device__ __forceinline__ float warp_red(float v) {
#pragma unroll
    for (int o = 16; o; o >>= 1) v += __shfl_xor_sync(0xffffffffu, v, o);
    return v;
}

// Software grid barrier: release via threadfence + atomic arrival; acquire via
// volatile spin + threadfence. All 1024 blocks are co-resident (7/SM * 148 = 1036).
__device__ __forceinline__ void gsync(int idx) {
    __syncthreads();
    if (threadIdx.x == 0) {
        __threadfence();
        unsigned arr = atomicAdd(&g_sync[idx], 1u);
        if (arr + 1u < (unsigned)GRID) {
            volatile unsigned* c = &g_sync[idx];
            while (*c < (unsigned)GRID) { }
        }
        __threadfence();
    }
    __syncthreads();
}

// Deterministic block-wide reduce of GRID partials; identical order in every
// block -> every block computes bit-identical alpha/beta. __ldcg: L2-coherent.
__device__ __forceinline__ float reduce_partials(const float* a, float* sred) {
    int tid = threadIdx.x;
    float s = 0.f;
#pragma unroll
    for (int k = 0; k < GRID / TPB; k++)
        s += __ldcg(a + tid + k * TPB);
    s = warp_red(s);
    if ((tid & 31) == 0) sred[tid >> 5] = s;
    __syncthreads();
    float tot = 0.f;
#pragma unroll
    for (int w = 0; w < TPB / 32; w++) tot += sred[w];
    __syncthreads();
    return tot;
}

__global__ void k_reset() {
    if (threadIdx.x < NSYNC) g_sync[threadIdx.x] = 0u;
}

__global__ void __launch_bounds__(TPB, 7) k_cg(const float* __restrict__ M,
                                               const float* __restrict__ RHS,
                                               float* __restrict__ out) {
    const int tid  = threadIdx.x;
    const int b    = blockIdx.x;
    const int w    = tid >> 5;
    const int lane = tid & 31;
    const int row  = b * ROWS_PB + w;

    __shared__ float sred[TPB / 32];
    __shared__ float sAp[ROWS_PB];   // M*p for own rows (recurrence)
    __shared__ float sP[ROWS_PB];    // p for own rows (recurrence)
    __shared__ float sX[ROWS_PB];    // X for own rows
    __shared__ float sR[ROWS_PB];    // r for own rows (mirror of g_r slice)

    // ---- init: X=0, r=RHS, p/Ap recurrences start at 0 (beta=0 handles iter 0)
    if (tid < ROWS_PB) {
        int i = b * ROWS_PB + tid;
        float v = RHS[i];
        g_r[i]   = v;
        sR[tid]  = v;
        sX[tid]  = 0.f;
        sP[tid]  = 0.f;
        sAp[tid] = 0.f;
    }
    __syncthreads();
    if (tid == 0) {
        float rs = 0.f;
#pragma unroll
        for (int k = 0; k < ROWS_PB; k++) rs += sR[k] * sR[k];
        g_rr[b] = rs;
    }
    gsync(2 * NITER);                       // r + rr partials globally visible
    float rtr  = reduce_partials(g_rr, sred);   // rTr0, identical in all blocks
    float beta = 0.f;

    int sidx = 0;
    for (int it = 0; it < NITER; it++) {
        if (!(rtr > TOLF)) break;           // uniform across all blocks

        // ---- matvec: acc = sum_j M[row][j] * r[j]  (Ar)
        const float4* __restrict__ Mr =
            reinterpret_cast<const float4*>(M) + (size_t)row * (N / 4);
        const float4* __restrict__ r4 = reinterpret_cast<const float4*>(g_r);
        float a0 = 0.f, a1 = 0.f;
#pragma unroll 4
        for (int j = lane; j < N / 4; j += 64) {
            float4 m0 = __ldcs(Mr + j);
            float4 m1 = __ldcs(Mr + j + 32);
            float4 v0 = __ldcg(r4 + j);
            float4 v1 = __ldcg(r4 + j + 32);
            a0 = fmaf(m0.x, v0.x, a0);
            a0 = fmaf(m0.y, v0.y, a0);
            a0 = fmaf(m0.z, v0.z, a0);
            a0 = fmaf(m0.w, v0.w, a0);
            a1 = fmaf(m1.x, v1.x, a1);
            a1 = fmaf(m1.y, v1.y, a1);
            a1 = fmaf(m1.z, v1.z, a1);
            a1 = fmaf(m1.w, v1.w, a1);
        }
        float acc = warp_red(a0 + a1);

        // ---- recurrences: Ap = Ar + beta*Ap_prev ; p = r + beta*p_prev
        if (lane == 0) {
            sAp[w] = fmaf(beta, sAp[w], acc);
            sP[w]  = fmaf(beta, sP[w], sR[w]);
        }
        __syncthreads();
        if (tid == 0) {
            float ps = 0.f;
#pragma unroll
            for (int k = 0; k < ROWS_PB; k++) ps += sP[k] * sAp[k];
            g_pap[b] = ps;
        }
        gsync(sidx++);

        float pAp   = reduce_partials(g_pap, sred);
        float alpha = rtr / pAp;

        // ---- update own slice of X and r; publish rr partial
        if (tid < ROWS_PB) {
            int i = b * ROWS_PB + tid;
            sX[tid]  = fmaf(alpha, sP[tid], sX[tid]);
            float rn = fmaf(-alpha, sAp[tid], sR[tid]);
            sR[tid]  = rn;
            g_r[i]   = rn;
        }
        __syncthreads();
        if (tid == 0) {
            float rs = 0.f;
#pragma unroll
            for (int k = 0; k < ROWS_PB; k++) rs += sR[k] * sR[k];
            g_rr[b] = rs;
        }
        gsync(sidx++);

        float rrn = reduce_partials(g_rr, sred);
        beta = rrn / rtr;
        rtr  = rrn;
    }

    if (tid < ROWS_PB) out[b * ROWS_PB + tid] = sX[tid];
}

extern "C" void kernel_launch(void* const* d_in, const int* in_sizes, int n_in,
                              void* d_out, int out_size) {
    // metadata order: X (shape only), M, RHS
    const float* M   = (const float*)d_in[1];
    const float* RHS = (const float*)d_in[2];
    float* out = (float*)d_out;

    k_reset<<<1, 64>>>();
    k_cg<<<GRID, TPB>>>(M, RHS, out);
}

// round 3
// speedup vs baseline: 1.3119x; 1.2962x over previous
#include <cuda_runtime.h>

#define N 8192
#define NITER 20
#define TOLF 1e-10f
#define GRID 512
#define TPB 256
#define ROWS_PB 16           // 2 rows per warp (8 warps)
#define NV4 (N / 4)          // 2048 float4 per row
#define RES_BLOCKS 192       // blocks 0..191 -> rows 0..3071 (96 MB) L2-resident policy
#define NSYNC (2 * NITER + 2)

// Persistent device state (no allocations allowed)
__device__ float g_r[N];
__device__ float g_pap[GRID];
__device__ float g_rr[GRID];
__device__ unsigned g_sync[NSYNC];

__device__ __forceinline__ float warp_red(float v) {
#pragma unroll
    for (int o = 16; o; o >>= 1) v += __shfl_xor_sync(0xffffffffu, v, o);
    return v;
}

// Software grid barrier (all 512 blocks co-resident: 4/SM * 148 = 592).
__device__ __forceinline__ void gsync(int idx) {
    __syncthreads();
    if (threadIdx.x == 0) {
        __threadfence();
        unsigned arr = atomicAdd(&g_sync[idx], 1u);
        if (arr + 1u < (unsigned)GRID) {
            volatile unsigned* c = &g_sync[idx];
            while (*c < (unsigned)GRID) { }
        }
        __threadfence();
    }
    __syncthreads();
}

// Deterministic reduce of GRID partials; identical order in every block.
__device__ __forceinline__ float reduce_partials(const float* a, float* sred) {
    int tid = threadIdx.x;
    float s = 0.f;
#pragma unroll
    for (int k = 0; k < GRID / TPB; k++)
        s += __ldcg(a + tid + k * TPB);
    s = warp_red(s);
    if ((tid & 31) == 0) sred[tid >> 5] = s;
    __syncthreads();
    float tot = 0.f;
#pragma unroll
    for (int w = 0; w < TPB / 32; w++) tot += sred[w];
    __syncthreads();
    return tot;
}

__global__ void k_reset() {
    if (threadIdx.x < NSYNC) g_sync[threadIdx.x] = 0u;
}

__global__ void __launch_bounds__(TPB, 4) k_cg(const float* __restrict__ M,
                                               const float* __restrict__ RHS,
                                               float* __restrict__ out) {
    const int tid  = threadIdx.x;
    const int b    = blockIdx.x;
    const int w    = tid >> 5;
    const int lane = tid & 31;
    const int row0 = b * ROWS_PB + w;        // warp's first row
    const int row1 = row0 + 8;               // warp's second row

    __shared__ __align__(16) float sp[N];    // full r vector staged per iteration (32 KB)
    __shared__ float sred[TPB / 32];
    __shared__ float sAcc[ROWS_PB];          // raw M*r for own rows this iter
    __shared__ float sAp[ROWS_PB];           // Ap recurrence
    __shared__ float sP[ROWS_PB];            // p recurrence
    __shared__ float sX[ROWS_PB];
    __shared__ float sR[ROWS_PB];

    // ---- init: X=0, r=RHS, recurrences start at 0 (beta=0 at iter 0)
    if (tid < ROWS_PB) {
        int i = b * ROWS_PB + tid;
        float v = RHS[i];
        g_r[i]   = v;
        sR[tid]  = v;
        sX[tid]  = 0.f;
        sP[tid]  = 0.f;
        sAp[tid] = 0.f;
    }
    __syncthreads();
    if (tid == 0) {
        float rs = 0.f;
#pragma unroll
        for (int k = 0; k < ROWS_PB; k++) rs += sR[k] * sR[k];
        g_rr[b] = rs;
    }
    gsync(2 * NITER);
    float rtr  = reduce_partials(g_rr, sred);
    float beta = 0.f;

    const float4* __restrict__ Mr0 = reinterpret_cast<const float4*>(M) + (size_t)row0 * NV4;
    const float4* __restrict__ Mr1 = reinterpret_cast<const float4*>(M) + (size_t)row1 * NV4;
    const bool resident = (b < RES_BLOCKS);

    int sidx = 0;
    for (int it = 0; it < NITER; it++) {
        if (!(rtr > TOLF)) break;            // uniform

        // ---- stage r into shared (coalesced float4)
        {
            const float4* r4 = reinterpret_cast<const float4*>(g_r);
            float4* sp4 = reinterpret_cast<float4*>(sp);
#pragma unroll
            for (int j = 0; j < NV4 / TPB; j++)
                sp4[tid + j * TPB] = __ldcg(r4 + tid + j * TPB);
        }
        __syncthreads();

        // ---- matvec: two rows per warp, r from shared
        const float4* sp4 = reinterpret_cast<const float4*>(sp);
        float a0 = 0.f, a1 = 0.f;
        if (resident) {
#pragma unroll 4
            for (int j = lane; j < NV4; j += 32) {
                float4 m0 = __ldg(Mr0 + j);        // default policy: L2-retained
                float4 m1 = __ldg(Mr1 + j);
                float4 v  = sp4[j];
                a0 = fmaf(m0.x, v.x, a0); a0 = fmaf(m0.y, v.y, a0);
                a0 = fmaf(m0.z, v.z, a0); a0 = fmaf(m0.w, v.w, a0);
                a1 = fmaf(m1.x, v.x, a1); a1 = fmaf(m1.y, v.y, a1);
                a1 = fmaf(m1.z, v.z, a1); a1 = fmaf(m1.w, v.w, a1);
            }
        } else {
#pragma unroll 4
            for (int j = lane; j < NV4; j += 32) {
                float4 m0 = __ldcs(Mr0 + j);       // streaming: evict-first
                float4 m1 = __ldcs(Mr1 + j);
                float4 v  = sp4[j];
                a0 = fmaf(m0.x, v.x, a0); a0 = fmaf(m0.y, v.y, a0);
                a0 = fmaf(m0.z, v.z, a0); a0 = fmaf(m0.w, v.w, a0);
                a1 = fmaf(m1.x, v.x, a1); a1 = fmaf(m1.y, v.y, a1);
                a1 = fmaf(m1.z, v.z, a1); a1 = fmaf(m1.w, v.w, a1);
            }
        }
        a0 = warp_red(a0);
        a1 = warp_red(a1);
        if (lane == 0) { sAcc[w] = a0; sAcc[w + 8] = a1; }
        __syncthreads();

        // ---- recurrences + pAp partial
        if (tid < ROWS_PB) {
            sAp[tid] = fmaf(beta, sAp[tid], sAcc[tid]);
            sP[tid]  = fmaf(beta, sP[tid], sR[tid]);
        }
        __syncthreads();
        if (tid == 0) {
            float ps = 0.f;
#pragma unroll
            for (int k = 0; k < ROWS_PB; k++) ps += sP[k] * sAp[k];
            g_pap[b] = ps;
        }
        gsync(sidx++);

        float pAp   = reduce_partials(g_pap, sred);
        float alpha = rtr / pAp;

        // ---- update own slice of X and r; publish rr partial
        if (tid < ROWS_PB) {
            int i = b * ROWS_PB + tid;
            sX[tid]  = fmaf(alpha, sP[tid], sX[tid]);
            float rn = fmaf(-alpha, sAp[tid], sR[tid]);
            sR[tid]  = rn;
            g_r[i]   = rn;
        }
        __syncthreads();
        if (tid == 0) {
            float rs = 0.f;
#pragma unroll
            for (int k = 0; k < ROWS_PB; k++) rs += sR[k] * sR[k];
            g_rr[b] = rs;
        }
        gsync(sidx++);

        float rrn = reduce_partials(g_rr, sred);
        beta = rrn / rtr;
        rtr  = rrn;
    }

    if (tid < ROWS_PB) out[b * ROWS_PB + tid] = sX[tid];
}

extern "C" void kernel_launch(void* const* d_in, const int* in_sizes, int n_in,
                              void* d_out, int out_size) {
    // metadata order: X (shape only), M, RHS
    const float* M   = (const float*)d_in[1];
    const float* RHS = (const float*)d_in[2];
    float* out = (float*)d_out;

    k_reset<<<1, 64>>>();
    k_cg<<<GRID, TPB>>>(M, RHS, out);
}

// round 4
// speedup vs baseline: 2.0972x; 1.5987x over previous
#include <cuda_runtime.h>

#define N 8192
#define NITER 20
#define TOLF 1e-10f
#define TDIM 256                        // tile edge
#define NTB (N / TDIM)                  // 32 tile-blocks per dimension
#define NTILES (NTB * (NTB + 1) / 2)    // 528 upper-triangle tiles
#define GRID NTILES
#define TPB 256
#define OWNERS 512                      // blocks owning vector slices
#define ROWS_PB (N / OWNERS)            // 16 rows per owner
#define PAP_PAD 768
#define RES_T 432                       // tiles < RES_T: default L2 policy (108 MB)
#define NSYNC (3 * NITER + 1)

// Persistent device state (no allocations allowed)
__device__ float g_p[N];
__device__ float g_ypart[NTB][NTB][TDIM];   // [row-block][contrib idx][elem], 1 MB
__device__ float g_pap[PAP_PAD];            // 528 used, rest stays 0
__device__ float g_rr[OWNERS];
__device__ unsigned g_sync[NSYNC];

__device__ __forceinline__ float warp_red(float v) {
#pragma unroll
    for (int o = 16; o; o >>= 1) v += __shfl_xor_sync(0xffffffffu, v, o);
    return v;
}

// Software grid barrier; all GRID blocks co-resident (4/SM * 148 = 592 >= 528).
__device__ __forceinline__ void gsync(int idx) {
    __syncthreads();
    if (threadIdx.x == 0) {
        __threadfence();
        unsigned arr = atomicAdd(&g_sync[idx], 1u);
        if (arr + 1u < (unsigned)GRID) {
            volatile unsigned* c = &g_sync[idx];
            while (*c < (unsigned)GRID) { }
        }
        __threadfence();
    }
    __syncthreads();
}

// Deterministic reduce of g_pap (768, zero-padded) — identical in every block.
__device__ __forceinline__ float reduce_pap(float* sred) {
    int tid = threadIdx.x;
    float s = 0.f;
#pragma unroll
    for (int k = 0; k < PAP_PAD / TPB; k++)
        s += __ldcg(g_pap + tid + k * TPB);
    s = warp_red(s);
    if ((tid & 31) == 0) sred[tid >> 5] = s;
    __syncthreads();
    float tot = 0.f;
#pragma unroll
    for (int w = 0; w < TPB / 32; w++) tot += sred[w];
    __syncthreads();
    return tot;
}

// Deterministic reduce of g_rr (512).
__device__ __forceinline__ float reduce_rr(float* sred) {
    int tid = threadIdx.x;
    float s = 0.f;
#pragma unroll
    for (int k = 0; k < OWNERS / TPB; k++)
        s += __ldcg(g_rr + tid + k * TPB);
    s = warp_red(s);
    if ((tid & 31) == 0) sred[tid >> 5] = s;
    __syncthreads();
    float tot = 0.f;
#pragma unroll
    for (int w = 0; w < TPB / 32; w++) tot += sred[w];
    __syncthreads();
    return tot;
}

__global__ void k_reset() {
    int t = threadIdx.x;
    if (t < NSYNC) g_sync[t] = 0u;
    if (t >= NTILES && t < PAP_PAD) g_pap[t] = 0.f;   // zero padding, never rewritten
}

__device__ __forceinline__ float dot8(float4 a0, float4 b0, float4 a1, float4 b1) {
    float s = 0.f;
    s = fmaf(a0.x, b0.x, s); s = fmaf(a0.y, b0.y, s);
    s = fmaf(a0.z, b0.z, s); s = fmaf(a0.w, b0.w, s);
    s = fmaf(a1.x, b1.x, s); s = fmaf(a1.y, b1.y, s);
    s = fmaf(a1.z, b1.z, s); s = fmaf(a1.w, b1.w, s);
    return s;
}

__global__ void __launch_bounds__(TPB, 4) k_cg(const float* __restrict__ M,
                                               const float* __restrict__ RHS,
                                               float* __restrict__ out) {
    const int tid  = threadIdx.x;
    const int b    = blockIdx.x;
    const int w    = tid >> 5;
    const int lane = tid & 31;

    // ---- decode upper-triangle tile index (ti <= tj)
    int ti = 0, rem = b;
    while (rem >= NTB - ti) { rem -= NTB - ti; ti++; }
    const int tj = ti + rem;
    const bool diag = (ti == tj);
    const bool resident = (b < RES_T);
    const bool owner = (b < OWNERS);

    __shared__ __align__(16) float sp_i[TDIM];
    __shared__ __align__(16) float sp_j[TDIM];
    __shared__ __align__(16) float scol[8][TDIM];  // per-warp column partials (8 KB)
    __shared__ float syrow[TDIM];
    __shared__ float sred[TPB / 32];
    __shared__ float sX[ROWS_PB], sR[ROWS_PB], sP[ROWS_PB], sAp[ROWS_PB];

    // ---- init: p = r = RHS, X = 0; rr partials
    if (owner && tid < ROWS_PB) {
        int i = b * ROWS_PB + tid;
        float v = RHS[i];
        g_p[i]  = v;
        sR[tid] = v;
        sP[tid] = v;
        sX[tid] = 0.f;
    }
    __syncthreads();
    if (owner && tid == 0) {
        float rs = 0.f;
#pragma unroll
        for (int k = 0; k < ROWS_PB; k++) rs += sR[k] * sR[k];
        g_rr[b] = rs;
    }
    int sidx = 0;
    gsync(sidx++);
    float rtr = reduce_rr(sred);

    const float4* __restrict__ M4 = reinterpret_cast<const float4*>(M);
    // warp's first row of this tile and column base, in float4 units
    const size_t row_base = (size_t)(ti * TDIM + w * 32) * (N / 4) + (size_t)tj * (TDIM / 4);

    for (int it = 0; it < NITER; it++) {
        if (!(rtr > TOLF)) break;                 // uniform across all blocks

        // ================= Phase 1: tile products =================
        sp_i[tid] = __ldcg(g_p + ti * TDIM + tid);
        sp_j[tid] = __ldcg(g_p + tj * TDIM + tid);
        __syncthreads();

        const float4* spj4 = reinterpret_cast<const float4*>(sp_j);
        const float4 v0 = spj4[lane];
        const float4 v1 = spj4[32 + lane];

        float4 acc0 = {0.f, 0.f, 0.f, 0.f};
        float4 acc1 = {0.f, 0.f, 0.f, 0.f};

#pragma unroll 2
        for (int r = 0; r < 32; r += 2) {
            const float4* p0 = M4 + row_base + (size_t)r * (N / 4);
            const float4* p1 = p0 + (N / 4);
            float4 m00, m01, m10, m11;
            if (resident) {
                m00 = __ldg(p0 + lane);  m01 = __ldg(p0 + 32 + lane);
                m10 = __ldg(p1 + lane);  m11 = __ldg(p1 + 32 + lane);
            } else {
                m00 = __ldcs(p0 + lane); m01 = __ldcs(p0 + 32 + lane);
                m10 = __ldcs(p1 + lane); m11 = __ldcs(p1 + 32 + lane);
            }
            float y0 = warp_red(dot8(m00, v0, m01, v1));
            float y1 = warp_red(dot8(m10, v0, m11, v1));
            if (lane == 0) { syrow[32 * w + r] = y0; syrow[32 * w + r + 1] = y1; }
            if (!diag) {
                float pi0 = sp_i[32 * w + r];
                float pi1 = sp_i[32 * w + r + 1];
                acc0.x = fmaf(m00.x, pi0, acc0.x); acc0.y = fmaf(m00.y, pi0, acc0.y);
                acc0.z = fmaf(m00.z, pi0, acc0.z); acc0.w = fmaf(m00.w, pi0, acc0.w);
                acc1.x = fmaf(m01.x, pi0, acc1.x); acc1.y = fmaf(m01.y, pi0, acc1.y);
                acc1.z = fmaf(m01.z, pi0, acc1.z); acc1.w = fmaf(m01.w, pi0, acc1.w);
                acc0.x = fmaf(m10.x, pi1, acc0.x); acc0.y = fmaf(m10.y, pi1, acc0.y);
                acc0.z = fmaf(m10.z, pi1, acc0.z); acc0.w = fmaf(m10.w, pi1, acc0.w);
                acc1.x = fmaf(m11.x, pi1, acc1.x); acc1.y = fmaf(m11.y, pi1, acc1.y);
                acc1.z = fmaf(m11.z, pi1, acc1.z); acc1.w = fmaf(m11.w, pi1, acc1.w);
            }
        }
        if (!diag) {
            float4* sc4 = reinterpret_cast<float4*>(scol[w]);
            sc4[lane]      = acc0;
            sc4[32 + lane] = acc1;
        }
        __syncthreads();

        // write ypart + per-tile pAp contribution
        float yr = syrow[tid];
        g_ypart[ti][tj][tid] = yr;
        float papc = yr * sp_i[tid];
        if (!diag) {
            float yc = 0.f;
#pragma unroll
            for (int ww = 0; ww < 8; ww++) yc += scol[ww][tid];
            g_ypart[tj][ti][tid] = yc;
            papc += yc * sp_j[tid];
        }
        float ps = warp_red(papc);
        if (lane == 0) sred[w] = ps;
        __syncthreads();
        if (tid == 0) {
            float s = 0.f;
#pragma unroll
            for (int ww = 0; ww < 8; ww++) s += sred[ww];
            g_pap[b] = s;
        }
        __syncthreads();
        gsync(sidx++);

        // ================= Phase 2: alpha; owners update X, r =================
        float pAp   = reduce_pap(sred);
        float alpha = rtr / pAp;

        if (owner) {
            // assemble Ap for own 16 rows: fixed-order 32-way sum each
            int R  = b >> 4;                  // row-block
            int e0 = (b & 15) * ROWS_PB;      // element base within row-block
            float s0 = __ldcg(&g_ypart[R][lane][e0 + 2 * w]);
            float s1 = __ldcg(&g_ypart[R][lane][e0 + 2 * w + 1]);
            s0 = warp_red(s0);
            s1 = warp_red(s1);
            if (lane == 0) { sAp[2 * w] = s0; sAp[2 * w + 1] = s1; }
        }
        __syncthreads();
        if (owner && tid < ROWS_PB) {
            sX[tid] = fmaf(alpha, sP[tid], sX[tid]);
            sR[tid] = fmaf(-alpha, sAp[tid], sR[tid]);
        }
        __syncthreads();
        if (owner && tid == 0) {
            float rs = 0.f;
#pragma unroll
            for (int k = 0; k < ROWS_PB; k++) rs += sR[k] * sR[k];
            g_rr[b] = rs;
        }
        gsync(sidx++);

        // ================= Phase 3: beta; owners update p =================
        float rrn  = reduce_rr(sred);
        float beta = rrn / rtr;
        rtr = rrn;
        if (owner && tid < ROWS_PB) {
            float pn = fmaf(beta, sP[tid], sR[tid]);
            sP[tid] = pn;
            g_p[b * ROWS_PB + tid] = pn;
        }
        gsync(sidx++);   // p globally visible before next Phase 1
    }

    if (owner && tid < ROWS_PB) out[b * ROWS_PB + tid] = sX[tid];
}

extern "C" void kernel_launch(void* const* d_in, const int* in_sizes, int n_in,
                              void* d_out, int out_size) {
    // metadata order: X (shape only), M, RHS
    const float* M   = (const float*)d_in[1];
    const float* RHS = (const float*)d_in[2];
    float* out = (float*)d_out;

    k_reset<<<1, PAP_PAD>>>();
    k_cg<<<GRID, TPB>>>(M, RHS, out);
}

// round 5
// speedup vs baseline: 2.3436x; 1.1175x over previous
#include <cuda_runtime.h>

#define N 8192
#define NITER 20
#define TOLF 1e-10f
#define TDIM 256                        // tile edge
#define NTB (N / TDIM)                  // 32 tile-blocks per dimension
#define NTILES (NTB * (NTB + 1) / 2)    // 528 upper-triangle tiles
#define GRID NTILES
#define TPB 256
#define OWNERS 512                      // blocks owning vector slices
#define ROWS_PB (N / OWNERS)            // 16 rows per owner
#define PAP_PAD 768
#define RES_T 432                       // tiles < RES_T: default L2 policy
#define NSYNC (2 * NITER + 1)

// Persistent device state (no allocations allowed)
__device__ float g_r[N];
__device__ float g_ypart[NTB][NTB][TDIM];   // [row-block][contrib idx][elem], 1 MB
__device__ float g_pap[PAP_PAD];            // 528 used, rest stays 0
__device__ float g_rr[OWNERS];
__device__ unsigned g_sync[NSYNC];

__device__ __forceinline__ float warp_red(float v) {
#pragma unroll
    for (int o = 16; o; o >>= 1) v += __shfl_xor_sync(0xffffffffu, v, o);
    return v;
}

// Software grid barrier; all GRID blocks co-resident (4/SM * 148 = 592 >= 528).
__device__ __forceinline__ void gsync(int idx) {
    __syncthreads();
    if (threadIdx.x == 0) {
        __threadfence();
        unsigned arr = atomicAdd(&g_sync[idx], 1u);
        if (arr + 1u < (unsigned)GRID) {
            volatile unsigned* c = &g_sync[idx];
            while (*c < (unsigned)GRID) { }
        }
        __threadfence();
    }
    __syncthreads();
}

// Deterministic reduce of g_pap (zero-padded to 768) — identical in every block.
__device__ __forceinline__ float reduce_pap(float* sred) {
    int tid = threadIdx.x;
    float s = 0.f;
#pragma unroll
    for (int k = 0; k < PAP_PAD / TPB; k++)
        s += __ldcg(g_pap + tid + k * TPB);
    s = warp_red(s);
    if ((tid & 31) == 0) sred[tid >> 5] = s;
    __syncthreads();
    float tot = 0.f;
#pragma unroll
    for (int w = 0; w < TPB / 32; w++) tot += sred[w];
    __syncthreads();
    return tot;
}

// Deterministic reduce of g_rr (512).
__device__ __forceinline__ float reduce_rr(float* sred) {
    int tid = threadIdx.x;
    float s = 0.f;
#pragma unroll
    for (int k = 0; k < OWNERS / TPB; k++)
        s += __ldcg(g_rr + tid + k * TPB);
    s = warp_red(s);
    if ((tid & 31) == 0) sred[tid >> 5] = s;
    __syncthreads();
    float tot = 0.f;
#pragma unroll
    for (int w = 0; w < TPB / 32; w++) tot += sred[w];
    __syncthreads();
    return tot;
}

__global__ void k_reset() {
    int t = threadIdx.x;
    if (t < NSYNC) g_sync[t] = 0u;
    if (t >= NTILES && t < PAP_PAD) g_pap[t] = 0.f;   // zero padding, never rewritten
}

__device__ __forceinline__ float dot8(float4 a0, float4 b0, float4 a1, float4 b1) {
    float s = 0.f;
    s = fmaf(a0.x, b0.x, s); s = fmaf(a0.y, b0.y, s);
    s = fmaf(a0.z, b0.z, s); s = fmaf(a0.w, b0.w, s);
    s = fmaf(a1.x, b1.x, s); s = fmaf(a1.y, b1.y, s);
    s = fmaf(a1.z, b1.z, s); s = fmaf(a1.w, b1.w, s);
    return s;
}

__global__ void __launch_bounds__(TPB, 4) k_cg(const float* __restrict__ M,
                                               const float* __restrict__ RHS,
                                               float* __restrict__ out) {
    const int tid  = threadIdx.x;
    const int b    = blockIdx.x;
    const int w    = tid >> 5;
    const int lane = tid & 31;

    // ---- decode upper-triangle tile index (ti <= tj)
    int ti = 0, rem = b;
    while (rem >= NTB - ti) { rem -= NTB - ti; ti++; }
    const int tj = ti + rem;
    const bool diag = (ti == tj);
    const bool resident = (b < RES_T);
    const bool owner = (b < OWNERS);

    __shared__ __align__(16) float sp_i[TDIM];       // local p slice (row side)
    __shared__ __align__(16) float sp_j[TDIM];       // local p slice (col side)
    __shared__ float srow[TDIM][33];                 // per-lane row-dot partials (~34 KB)
    __shared__ __align__(16) float scol[8][TDIM];    // per-warp column partials (8 KB)
    __shared__ float sred[TPB / 32];
    __shared__ float sX[ROWS_PB], sR[ROWS_PB], sP[ROWS_PB], sAp[ROWS_PB];

    // ---- init: p = r = RHS locally; owners publish rr partials
    sp_i[tid] = __ldg(RHS + ti * TDIM + tid);
    sp_j[tid] = __ldg(RHS + tj * TDIM + tid);
    if (owner && tid < ROWS_PB) {
        int i = b * ROWS_PB + tid;
        float v = RHS[i];
        g_r[i]  = v;
        sR[tid] = v;
        sP[tid] = v;
        sX[tid] = 0.f;
    }
    __syncthreads();
    if (owner && tid == 0) {
        float rs = 0.f;
#pragma unroll
        for (int k = 0; k < ROWS_PB; k++) rs += sR[k] * sR[k];
        g_rr[b] = rs;
    }
    int sidx = 0;
    gsync(sidx++);
    float rtr = reduce_rr(sred);

    const float4* __restrict__ M4 = reinterpret_cast<const float4*>(M);
    const size_t row_base = (size_t)(ti * TDIM + w * 32) * (N / 4) + (size_t)tj * (TDIM / 4);

    for (int it = 0; it < NITER; it++) {
        if (!(rtr > TOLF)) break;                 // uniform across all blocks

        // ================= Phase 1: tile products (no cross-lane ops in loop) ====
        const float4* spj4 = reinterpret_cast<const float4*>(sp_j);
        const float4 v0 = spj4[lane];
        const float4 v1 = spj4[32 + lane];

        float4 acc0 = {0.f, 0.f, 0.f, 0.f};
        float4 acc1 = {0.f, 0.f, 0.f, 0.f};

#pragma unroll 2
        for (int r = 0; r < 32; r += 2) {
            const float4* p0 = M4 + row_base + (size_t)r * (N / 4);
            const float4* p1 = p0 + (N / 4);
            float4 m00, m01, m10, m11;
            if (resident) {
                m00 = __ldg(p0 + lane);  m01 = __ldg(p0 + 32 + lane);
                m10 = __ldg(p1 + lane);  m11 = __ldg(p1 + 32 + lane);
            } else {
                m00 = __ldcs(p0 + lane); m01 = __ldcs(p0 + 32 + lane);
                m10 = __ldcs(p1 + lane); m11 = __ldcs(p1 + 32 + lane);
            }
            // lane-local row-dot partials -> shared (no reduction here)
            srow[32 * w + r][lane]     = dot8(m00, v0, m01, v1);
            srow[32 * w + r + 1][lane] = dot8(m10, v0, m11, v1);
            if (!diag) {
                float pi0 = sp_i[32 * w + r];
                float pi1 = sp_i[32 * w + r + 1];
                acc0.x = fmaf(m00.x, pi0, acc0.x); acc0.y = fmaf(m00.y, pi0, acc0.y);
                acc0.z = fmaf(m00.z, pi0, acc0.z); acc0.w = fmaf(m00.w, pi0, acc0.w);
                acc1.x = fmaf(m01.x, pi0, acc1.x); acc1.y = fmaf(m01.y, pi0, acc1.y);
                acc1.z = fmaf(m01.z, pi0, acc1.z); acc1.w = fmaf(m01.w, pi0, acc1.w);
                acc0.x = fmaf(m10.x, pi1, acc0.x); acc0.y = fmaf(m10.y, pi1, acc0.y);
                acc0.z = fmaf(m10.z, pi1, acc0.z); acc0.w = fmaf(m10.w, pi1, acc0.w);
                acc1.x = fmaf(m11.x, pi1, acc1.x); acc1.y = fmaf(m11.y, pi1, acc1.y);
                acc1.z = fmaf(m11.z, pi1, acc1.z); acc1.w = fmaf(m11.w, pi1, acc1.w);
            }
        }
        if (!diag) {
            float4* sc4 = reinterpret_cast<float4*>(scol[w]);
            sc4[lane]      = acc0;
            sc4[32 + lane] = acc1;
        }
        __syncthreads();

        // deferred row reduce: thread t owns row t (conflict-free: stride-33 rows)
        float yr = 0.f;
#pragma unroll
        for (int k = 0; k < 32; k++) yr += srow[tid][k];
        g_ypart[ti][tj][tid] = yr;
        float papc = yr * sp_i[tid];
        if (!diag) {
            float yc = 0.f;
#pragma unroll
            for (int ww = 0; ww < 8; ww++) yc += scol[ww][tid];
            g_ypart[tj][ti][tid] = yc;
            papc += yc * sp_j[tid];
        }
        float ps = warp_red(papc);
        if (lane == 0) sred[w] = ps;
        __syncthreads();
        if (tid == 0) {
            float s = 0.f;
#pragma unroll
            for (int ww = 0; ww < 8; ww++) s += sred[ww];
            g_pap[b] = s;
        }
        __syncthreads();
        gsync(sidx++);

        // ================= Phase 2: alpha; owners update X, r, publish rr =======
        float pAp   = reduce_pap(sred);
        float alpha = rtr / pAp;

        if (owner) {
            int R  = b >> 4;                  // row-block
            int e0 = (b & 15) * ROWS_PB;      // element base within row-block
            float s0 = __ldcg(&g_ypart[R][lane][e0 + 2 * w]);
            float s1 = __ldcg(&g_ypart[R][lane][e0 + 2 * w + 1]);
            s0 = warp_red(s0);
            s1 = warp_red(s1);
            if (lane == 0) { sAp[2 * w] = s0; sAp[2 * w + 1] = s1; }
        }
        __syncthreads();
        if (owner && tid < ROWS_PB) {
            sX[tid]  = fmaf(alpha, sP[tid], sX[tid]);
            float rn = fmaf(-alpha, sAp[tid], sR[tid]);
            sR[tid]  = rn;
            g_r[b * ROWS_PB + tid] = rn;
        }
        __syncthreads();
        if (owner && tid == 0) {
            float rs = 0.f;
#pragma unroll
            for (int k = 0; k < ROWS_PB; k++) rs += sR[k] * sR[k];
            g_rr[b] = rs;
        }
        gsync(sidx++);

        // ================= Phase 3 (no sync): beta; local p recurrences =========
        float rrn  = reduce_rr(sred);
        float beta = rrn / rtr;
        rtr = rrn;
        // every replica of a p element computes the identical fma -> bitwise equal
        sp_i[tid] = fmaf(beta, sp_i[tid], __ldcg(g_r + ti * TDIM + tid));
        sp_j[tid] = fmaf(beta, sp_j[tid], __ldcg(g_r + tj * TDIM + tid));
        if (owner && tid < ROWS_PB)
            sP[tid] = fmaf(beta, sP[tid], sR[tid]);
        __syncthreads();
    }

    if (owner && tid < ROWS_PB) out[b * ROWS_PB + tid] = sX[tid];
}

extern "C" void kernel_launch(void* const* d_in, const int* in_sizes, int n_in,
                              void* d_out, int out_size) {
    // metadata order: X (shape only), M, RHS
    const float* M   = (const float*)d_in[1];
    const float* RHS = (const float*)d_in[2];
    float* out = (float*)d_out;

    k_reset<<<1, PAP_PAD>>>();
    k_cg<<<GRID, TPB>>>(M, RHS, out);
}